// round 1
// baseline (speedup 1.0000x reference)
#include <cuda_runtime.h>
#include <cuda_bf16.h>

#define N_USER 100000
#define N_ITEM 20000
#define N_NODES 120000
#define N_EDGES 2000000
#define EMB 64
#define VEC 16   // float4 chunks per 64-dim row

// ---- static scratch (no allocations allowed) ----
__device__ float g_x0[N_NODES * EMB];
__device__ float g_x1[N_NODES * EMB];
__device__ float g_x2[N_NODES * EMB];
__device__ int   g_deg[N_NODES];
__device__ float g_dis[N_NODES];
__device__ float g_norm[N_EDGES];

static inline int cdiv(int a, int b) { return (a + b - 1) / b; }

// ---------------------------------------------------------------------------
__global__ void k_zero_deg() {
    int n = blockIdx.x * blockDim.x + threadIdx.x;
    if (n < N_NODES) g_deg[n] = 0;
}

__global__ void k_zero_feat(float4* buf) {
    int t = blockIdx.x * blockDim.x + threadIdx.x;
    if (t < N_NODES * VEC) buf[t] = make_float4(0.f, 0.f, 0.f, 0.f);
}

__global__ void k_deg(const int* __restrict__ col) {
    int e = blockIdx.x * blockDim.x + threadIdx.x;
    if (e < N_EDGES) atomicAdd(&g_deg[col[e]], 1);
}

__global__ void k_dis() {
    int n = blockIdx.x * blockDim.x + threadIdx.x;
    if (n < N_NODES) {
        int d = g_deg[n];
        g_dis[n] = (d > 0) ? rsqrtf((float)d) : 0.0f;
    }
}

__global__ void k_norm(const int* __restrict__ row, const int* __restrict__ col) {
    int e = blockIdx.x * blockDim.x + threadIdx.x;
    if (e < N_EDGES) g_norm[e] = g_dis[row[e]] * g_dis[col[e]];
}

// x0: users copied, items = mean of 4 embeddings
__global__ void k_x0(const float4* __restrict__ user_emb,
                     const float4* __restrict__ item_emb,
                     const int*    __restrict__ tag,
                     const int*    __restrict__ testid,
                     const int*    __restrict__ bigcat,
                     const float4* __restrict__ tag_emb,
                     const float4* __restrict__ testid_emb,
                     const float4* __restrict__ bigcat_emb) {
    int t = blockIdx.x * blockDim.x + threadIdx.x;
    if (t >= N_NODES * VEC) return;
    int n = t >> 4, q = t & 15;
    float4* out = reinterpret_cast<float4*>(g_x0);
    if (n < N_USER) {
        out[t] = user_emb[n * VEC + q];
    } else {
        int i = n - N_USER;
        float4 a = item_emb[i * VEC + q];
        float4 b = tag_emb[tag[i] * VEC + q];
        float4 c = testid_emb[testid[i] * VEC + q];
        float4 d = bigcat_emb[bigcat[i] * VEC + q];
        out[t] = make_float4((a.x + b.x + c.x + d.x) * 0.25f,
                             (a.y + b.y + c.y + d.y) * 0.25f,
                             (a.z + b.z + c.z + d.z) * 0.25f,
                             (a.w + b.w + c.w + d.w) * 0.25f);
    }
}

// One float4 per thread, 16 threads per edge. red.global.add.v4.f32 scatter.
__global__ void k_scatter(const int* __restrict__ row, const int* __restrict__ col,
                          const float4* __restrict__ xin, float4* __restrict__ xout) {
    int t = blockIdx.x * blockDim.x + threadIdx.x;
    if (t >= N_EDGES * VEC) return;
    int e = t >> 4, q = t & 15;
    int r = row[e], c = col[e];
    float nv = g_norm[e];
    float4 v = xin[r * VEC + q];
    v.x *= nv; v.y *= nv; v.z *= nv; v.w *= nv;
    float4* dst = xout + c * VEC + q;
    asm volatile("red.global.add.v4.f32 [%0], {%1,%2,%3,%4};"
                 :: "l"(dst), "f"(v.x), "f"(v.y), "f"(v.z), "f"(v.w)
                 : "memory");
}

// out = a0*x0 + a1*x1 + a2*x2, written back into g_x0
__global__ void k_combine(const float* __restrict__ alpha) {
    int t = blockIdx.x * blockDim.x + threadIdx.x;
    if (t >= N_NODES * VEC) return;
    float a0 = alpha[0], a1 = alpha[1], a2 = alpha[2];
    float4 x = reinterpret_cast<float4*>(g_x0)[t];
    float4 y = reinterpret_cast<float4*>(g_x1)[t];
    float4 z = reinterpret_cast<float4*>(g_x2)[t];
    reinterpret_cast<float4*>(g_x0)[t] =
        make_float4(a0 * x.x + a1 * y.x + a2 * z.x,
                    a0 * x.y + a1 * y.y + a2 * z.y,
                    a0 * x.z + a1 * y.z + a2 * z.z,
                    a0 * x.w + a1 * y.w + a2 * z.w);
}

// 16 lanes per edge: float4 partial dot + shfl tree reduce within the 16-group
__global__ void k_dot(const int* __restrict__ row, const int* __restrict__ col,
                      float* __restrict__ out) {
    int t = blockIdx.x * blockDim.x + threadIdx.x;
    if (t >= N_EDGES * VEC) return;
    int e = t >> 4, q = t & 15;
    const float4* x = reinterpret_cast<const float4*>(g_x0);
    float4 a = x[row[e] * VEC + q];
    float4 b = x[col[e] * VEC + q];
    float s = a.x * b.x + a.y * b.y + a.z * b.z + a.w * b.w;
    s += __shfl_xor_sync(0xffffffffu, s, 8);
    s += __shfl_xor_sync(0xffffffffu, s, 4);
    s += __shfl_xor_sync(0xffffffffu, s, 2);
    s += __shfl_xor_sync(0xffffffffu, s, 1);
    if (q == 0) out[e] = s;
}

// ---------------------------------------------------------------------------
extern "C" void kernel_launch(void* const* d_in, const int* in_sizes, int n_in,
                              void* d_out, int out_size) {
    const int*    edge_index = (const int*)d_in[0];       // [2, E]
    const int*    item_tag   = (const int*)d_in[1];
    const int*    item_testid= (const int*)d_in[2];
    const int*    item_bigcat= (const int*)d_in[3];
    const float4* user_emb   = (const float4*)d_in[4];
    const float4* item_emb   = (const float4*)d_in[5];
    const float4* tag_emb    = (const float4*)d_in[6];
    const float4* testid_emb = (const float4*)d_in[7];
    const float4* bigcat_emb = (const float4*)d_in[8];
    const float*  alpha      = (const float*)d_in[9];
    float* out = (float*)d_out;

    const int* row = edge_index;
    const int* col = edge_index + N_EDGES;

    const int B = 256;
    float4* x0 = nullptr; float4* x1 = nullptr; float4* x2 = nullptr;
    // device symbol addresses resolve at launch via kernel args not needed for
    // g_x0 etc. (referenced directly in device code); for zero/scatter we need
    // host-visible pointers:
    cudaGetSymbolAddress((void**)&x0, g_x0);
    cudaGetSymbolAddress((void**)&x1, g_x1);
    cudaGetSymbolAddress((void**)&x2, g_x2);

    // degree + norm
    k_zero_deg<<<cdiv(N_NODES, B), B>>>();
    k_deg<<<cdiv(N_EDGES, B), B>>>(col);
    k_dis<<<cdiv(N_NODES, B), B>>>();
    k_norm<<<cdiv(N_EDGES, B), B>>>(row, col);

    // x0 features
    k_x0<<<cdiv(N_NODES * VEC, B), B>>>(user_emb, item_emb, item_tag, item_testid,
                                        item_bigcat, tag_emb, testid_emb, bigcat_emb);

    // layer 1: x1 = A_hat @ x0
    k_zero_feat<<<cdiv(N_NODES * VEC, B), B>>>(x1);
    k_scatter<<<cdiv(N_EDGES * VEC, B), B>>>(row, col, x0, x1);

    // layer 2: x2 = A_hat @ x1
    k_zero_feat<<<cdiv(N_NODES * VEC, B), B>>>(x2);
    k_scatter<<<cdiv(N_EDGES * VEC, B), B>>>(row, col, x1, x2);

    // out embedding (into x0) and per-edge dots
    k_combine<<<cdiv(N_NODES * VEC, B), B>>>(alpha);
    k_dot<<<cdiv(N_EDGES * VEC, B), B>>>(row, col, out);
}

// round 2
// speedup vs baseline: 1.0097x; 1.0097x over previous
#include <cuda_runtime.h>
#include <cuda_fp16.h>

#define N_USER 100000
#define N_ITEM 20000
#define N_NODES 120000
#define N_EDGES 2000000
#define EMB 64
#define VEC 16   // float4 chunks per 64-float row
#define HVEC 16  // uint2 (4-half) chunks per 64-half row

// ---- static scratch (no allocations allowed) ----
__device__ float  g_x0[N_NODES * EMB];   // fp32 layer-0 features
__device__ float  g_x1[N_NODES * EMB];   // fp32 accumulators
__device__ float  g_x2[N_NODES * EMB];
__device__ __half g_h0[N_NODES * EMB];   // fp16 gather copies
__device__ __half g_h1[N_NODES * EMB];
__device__ int    g_deg[N_NODES];
__device__ float  g_dis[N_NODES];

static inline int cdiv(int a, int b) { return (a + b - 1) / b; }

// ---------------------------------------------------------------------------
__global__ void k_zero_deg() {
    int n = blockIdx.x * blockDim.x + threadIdx.x;
    if (n < N_NODES) g_deg[n] = 0;
}

__global__ void k_zero_feat(float4* buf) {
    int t = blockIdx.x * blockDim.x + threadIdx.x;
    if (t < N_NODES * VEC) buf[t] = make_float4(0.f, 0.f, 0.f, 0.f);
}

__global__ void k_deg(const int* __restrict__ col) {
    int e = blockIdx.x * blockDim.x + threadIdx.x;
    if (e < N_EDGES) atomicAdd(&g_deg[col[e]], 1);
}

__global__ void k_dis() {
    int n = blockIdx.x * blockDim.x + threadIdx.x;
    if (n < N_NODES) {
        int d = g_deg[n];
        g_dis[n] = (d > 0) ? rsqrtf((float)d) : 0.0f;
    }
}

// x0: users copied, items = mean of 4 embeddings. Writes fp32 + fp16 copies.
__global__ void k_x0(const float4* __restrict__ user_emb,
                     const float4* __restrict__ item_emb,
                     const int*    __restrict__ tag,
                     const int*    __restrict__ testid,
                     const int*    __restrict__ bigcat,
                     const float4* __restrict__ tag_emb,
                     const float4* __restrict__ testid_emb,
                     const float4* __restrict__ bigcat_emb) {
    int t = blockIdx.x * blockDim.x + threadIdx.x;
    if (t >= N_NODES * VEC) return;
    int n = t >> 4, q = t & 15;
    float4 v;
    if (n < N_USER) {
        v = user_emb[n * VEC + q];
    } else {
        int i = n - N_USER;
        float4 a = item_emb[i * VEC + q];
        float4 b = tag_emb[tag[i] * VEC + q];
        float4 c = testid_emb[testid[i] * VEC + q];
        float4 d = bigcat_emb[bigcat[i] * VEC + q];
        v = make_float4((a.x + b.x + c.x + d.x) * 0.25f,
                        (a.y + b.y + c.y + d.y) * 0.25f,
                        (a.z + b.z + c.z + d.z) * 0.25f,
                        (a.w + b.w + c.w + d.w) * 0.25f);
    }
    reinterpret_cast<float4*>(g_x0)[t] = v;
    __half2 pa = __floats2half2_rn(v.x, v.y);
    __half2 pb = __floats2half2_rn(v.z, v.w);
    reinterpret_cast<uint2*>(g_h0)[t] =
        make_uint2(*reinterpret_cast<unsigned*>(&pa), *reinterpret_cast<unsigned*>(&pb));
}

// fp32 -> fp16 sweep
__global__ void k_h_convert(const float4* __restrict__ src, uint2* __restrict__ dst) {
    int t = blockIdx.x * blockDim.x + threadIdx.x;
    if (t >= N_NODES * VEC) return;
    float4 v = src[t];
    __half2 pa = __floats2half2_rn(v.x, v.y);
    __half2 pb = __floats2half2_rn(v.z, v.w);
    dst[t] = make_uint2(*reinterpret_cast<unsigned*>(&pa), *reinterpret_cast<unsigned*>(&pb));
}

// 16 threads/edge: 8B fp16 gather each, fp32 red.v4 scatter. norm computed inline.
__global__ void k_scatter_h(const int* __restrict__ row, const int* __restrict__ col,
                            const uint2* __restrict__ hin, float4* __restrict__ xout) {
    long long t = (long long)blockIdx.x * blockDim.x + threadIdx.x;
    if (t >= (long long)N_EDGES * VEC) return;
    int e = (int)(t >> 4), q = (int)(t & 15);
    int r = row[e], c = col[e];
    float nv = g_dis[r] * g_dis[c];
    uint2 u = hin[r * HVEC + q];
    __half2 pa = *reinterpret_cast<__half2*>(&u.x);
    __half2 pb = *reinterpret_cast<__half2*>(&u.y);
    float2 f0 = __half22float2(pa);
    float2 f1 = __half22float2(pb);
    float4* dst = xout + c * VEC + q;
    asm volatile("red.global.add.v4.f32 [%0], {%1,%2,%3,%4};"
                 :: "l"(dst), "f"(f0.x * nv), "f"(f0.y * nv),
                    "f"(f1.x * nv), "f"(f1.y * nv)
                 : "memory");
}

// out = a0*x0 + a1*x1 + a2*x2, written as fp16 into g_h0
__global__ void k_combine_h(const float* __restrict__ alpha) {
    int t = blockIdx.x * blockDim.x + threadIdx.x;
    if (t >= N_NODES * VEC) return;
    float a0 = alpha[0], a1 = alpha[1], a2 = alpha[2];
    float4 x = reinterpret_cast<float4*>(g_x0)[t];
    float4 y = reinterpret_cast<float4*>(g_x1)[t];
    float4 z = reinterpret_cast<float4*>(g_x2)[t];
    float4 v = make_float4(a0 * x.x + a1 * y.x + a2 * z.x,
                           a0 * x.y + a1 * y.y + a2 * z.y,
                           a0 * x.z + a1 * y.z + a2 * z.z,
                           a0 * x.w + a1 * y.w + a2 * z.w);
    __half2 pa = __floats2half2_rn(v.x, v.y);
    __half2 pb = __floats2half2_rn(v.z, v.w);
    reinterpret_cast<uint2*>(g_h0)[t] =
        make_uint2(*reinterpret_cast<unsigned*>(&pa), *reinterpret_cast<unsigned*>(&pb));
}

// 16 lanes/edge: fp16 gathers both sides, fp32 math, shfl tree reduce
__global__ void k_dot_h(const int* __restrict__ row, const int* __restrict__ col,
                        float* __restrict__ out) {
    long long t = (long long)blockIdx.x * blockDim.x + threadIdx.x;
    if (t >= (long long)N_EDGES * VEC) return;
    int e = (int)(t >> 4), q = (int)(t & 15);
    const uint2* h = reinterpret_cast<const uint2*>(g_h0);
    uint2 ua = h[row[e] * HVEC + q];
    uint2 ub = h[col[e] * HVEC + q];
    float2 a0 = __half22float2(*reinterpret_cast<__half2*>(&ua.x));
    float2 a1 = __half22float2(*reinterpret_cast<__half2*>(&ua.y));
    float2 b0 = __half22float2(*reinterpret_cast<__half2*>(&ub.x));
    float2 b1 = __half22float2(*reinterpret_cast<__half2*>(&ub.y));
    float s = a0.x * b0.x + a0.y * b0.y + a1.x * b1.x + a1.y * b1.y;
    s += __shfl_xor_sync(0xffffffffu, s, 8);
    s += __shfl_xor_sync(0xffffffffu, s, 4);
    s += __shfl_xor_sync(0xffffffffu, s, 2);
    s += __shfl_xor_sync(0xffffffffu, s, 1);
    if (q == 0) out[e] = s;
}

// ---------------------------------------------------------------------------
extern "C" void kernel_launch(void* const* d_in, const int* in_sizes, int n_in,
                              void* d_out, int out_size) {
    const int*    edge_index = (const int*)d_in[0];       // [2, E]
    const int*    item_tag   = (const int*)d_in[1];
    const int*    item_testid= (const int*)d_in[2];
    const int*    item_bigcat= (const int*)d_in[3];
    const float4* user_emb   = (const float4*)d_in[4];
    const float4* item_emb   = (const float4*)d_in[5];
    const float4* tag_emb    = (const float4*)d_in[6];
    const float4* testid_emb = (const float4*)d_in[7];
    const float4* bigcat_emb = (const float4*)d_in[8];
    const float*  alpha      = (const float*)d_in[9];
    float* out = (float*)d_out;

    const int* row = edge_index;
    const int* col = edge_index + N_EDGES;

    const int B = 256;
    float4* x1 = nullptr; float4* x2 = nullptr;
    uint2* h0 = nullptr; uint2* h1 = nullptr;
    cudaGetSymbolAddress((void**)&x1, g_x1);
    cudaGetSymbolAddress((void**)&x2, g_x2);
    cudaGetSymbolAddress((void**)&h0, g_h0);
    cudaGetSymbolAddress((void**)&h1, g_h1);

    // degree + inv-sqrt
    k_zero_deg<<<cdiv(N_NODES, B), B>>>();
    k_deg<<<cdiv(N_EDGES, B), B>>>(col);
    k_dis<<<cdiv(N_NODES, B), B>>>();

    // x0 features (fp32 + fp16 copies)
    k_x0<<<cdiv(N_NODES * VEC, B), B>>>(user_emb, item_emb, item_tag, item_testid,
                                        item_bigcat, tag_emb, testid_emb, bigcat_emb);

    // layer 1: x1 = A_hat @ x0   (fp16 gathers, fp32 accumulation)
    k_zero_feat<<<cdiv(N_NODES * VEC, B), B>>>(x1);
    k_scatter_h<<<cdiv(N_EDGES * VEC, B), B>>>(row, col, h0, x1);
    k_h_convert<<<cdiv(N_NODES * VEC, B), B>>>(x1, h1);

    // layer 2: x2 = A_hat @ x1
    k_zero_feat<<<cdiv(N_NODES * VEC, B), B>>>(x2);
    k_scatter_h<<<cdiv(N_EDGES * VEC, B), B>>>(row, col, h1, x2);

    // combined embedding (fp16 into g_h0) and per-edge dots
    k_combine_h<<<cdiv(N_NODES * VEC, B), B>>>(alpha);
    k_dot_h<<<cdiv(N_EDGES * VEC, B), B>>>(row, col, out);
}

// round 3
// speedup vs baseline: 1.5639x; 1.5489x over previous
#include <cuda_runtime.h>
#include <cuda_fp16.h>

#define N_USER 100000
#define N_ITEM 20000
#define N_NODES 120000
#define N_EDGES 2000000
#define EMB 64
#define VEC 16      // 4-element chunks per 64-dim row
#define NB_SCAN 469 // cdiv(N_NODES, 256)

// ---- static scratch (no allocations allowed) ----
__device__ __half g_h0[N_NODES * EMB];   // fp16 feature buffers
__device__ __half g_h1[N_NODES * EMB];
__device__ __half g_h2[N_NODES * EMB];
__device__ __half g_ho[N_NODES * EMB];   // combined output embedding
__device__ int    g_deg[N_NODES];
__device__ int    g_cnt[N_NODES];
__device__ int    g_rowptr[N_NODES];
__device__ int    g_bsum[512];
__device__ float  g_dis[N_NODES];
__device__ uint2  g_adj[N_EDGES];        // {src, norm bits} grouped by dst

static inline int cdiv(int a, int b) { return (a + b - 1) / b; }

// ---------------------------------------------------------------------------
__global__ void k_zero_counts() {
    int n = blockIdx.x * blockDim.x + threadIdx.x;
    if (n < N_NODES) { g_deg[n] = 0; g_cnt[n] = 0; }
}

__global__ void k_deg(const int* __restrict__ col) {
    int e = blockIdx.x * blockDim.x + threadIdx.x;
    if (e < N_EDGES) atomicAdd(&g_deg[col[e]], 1);
}

__global__ void k_dis() {
    int n = blockIdx.x * blockDim.x + threadIdx.x;
    if (n < N_NODES) {
        int d = g_deg[n];
        g_dis[n] = (d > 0) ? rsqrtf((float)d) : 0.0f;
    }
}

// ---- 3-kernel exclusive scan of g_deg -> g_rowptr ----
__global__ void k_scan_a() {
    __shared__ int sh[256];
    int i = blockIdx.x * 256 + threadIdx.x;
    sh[threadIdx.x] = (i < N_NODES) ? g_deg[i] : 0;
    __syncthreads();
    for (int s = 128; s > 0; s >>= 1) {
        if (threadIdx.x < s) sh[threadIdx.x] += sh[threadIdx.x + s];
        __syncthreads();
    }
    if (threadIdx.x == 0) g_bsum[blockIdx.x] = sh[0];
}

__global__ void k_scan_b() {
    __shared__ int sh[512];
    int t = threadIdx.x;
    int v = (t < NB_SCAN) ? g_bsum[t] : 0;
    sh[t] = v;
    __syncthreads();
    for (int off = 1; off < 512; off <<= 1) {
        int x = (t >= off) ? sh[t - off] : 0;
        __syncthreads();
        sh[t] += x;
        __syncthreads();
    }
    if (t < NB_SCAN) g_bsum[t] = sh[t] - v;   // exclusive prefix of block sums
}

__global__ void k_scan_c() {
    __shared__ int sh[256];
    int i = blockIdx.x * 256 + threadIdx.x;
    int v = (i < N_NODES) ? g_deg[i] : 0;
    sh[threadIdx.x] = v;
    __syncthreads();
    for (int off = 1; off < 256; off <<= 1) {
        int x = (threadIdx.x >= off) ? sh[threadIdx.x - off] : 0;
        __syncthreads();
        sh[threadIdx.x] += x;
        __syncthreads();
    }
    if (i < N_NODES) g_rowptr[i] = g_bsum[blockIdx.x] + sh[threadIdx.x] - v;
}

// ---- CSR fill: slot per edge under its destination ----
__global__ void k_fill(const int* __restrict__ row, const int* __restrict__ col) {
    int e = blockIdx.x * blockDim.x + threadIdx.x;
    if (e >= N_EDGES) return;
    int r = row[e], c = col[e];
    float nv = g_dis[r] * g_dis[c];
    int pos = g_rowptr[c] + atomicAdd(&g_cnt[c], 1);
    g_adj[pos] = make_uint2((unsigned)r, __float_as_uint(nv));
}

// ---- x0: users copied, items = mean of 4 embeddings; fp16 out ----
__global__ void k_x0(const float4* __restrict__ user_emb,
                     const float4* __restrict__ item_emb,
                     const int*    __restrict__ tag,
                     const int*    __restrict__ testid,
                     const int*    __restrict__ bigcat,
                     const float4* __restrict__ tag_emb,
                     const float4* __restrict__ testid_emb,
                     const float4* __restrict__ bigcat_emb) {
    int t = blockIdx.x * blockDim.x + threadIdx.x;
    if (t >= N_NODES * VEC) return;
    int n = t >> 4, q = t & 15;
    float4 v;
    if (n < N_USER) {
        v = user_emb[n * VEC + q];
    } else {
        int i = n - N_USER;
        float4 a = item_emb[i * VEC + q];
        float4 b = tag_emb[tag[i] * VEC + q];
        float4 c = testid_emb[testid[i] * VEC + q];
        float4 d = bigcat_emb[bigcat[i] * VEC + q];
        v = make_float4((a.x + b.x + c.x + d.x) * 0.25f,
                        (a.y + b.y + c.y + d.y) * 0.25f,
                        (a.z + b.z + c.z + d.z) * 0.25f,
                        (a.w + b.w + c.w + d.w) * 0.25f);
    }
    __half2 pa = __floats2half2_rn(v.x, v.y);
    __half2 pb = __floats2half2_rn(v.z, v.w);
    reinterpret_cast<uint2*>(g_h0)[t] =
        make_uint2(*reinterpret_cast<unsigned*>(&pa), *reinterpret_cast<unsigned*>(&pb));
}

// ---- pull-based propagation: 16 lanes per dst node, register accumulation ----
__global__ void k_gather(const uint2* __restrict__ hin, uint2* __restrict__ hout) {
    int t = blockIdx.x * blockDim.x + threadIdx.x;
    if (t >= N_NODES * VEC) return;
    int n = t >> 4, q = t & 15;
    int start = g_rowptr[n];
    int end = start + g_deg[n];
    float4 acc = make_float4(0.f, 0.f, 0.f, 0.f);
    #pragma unroll 2
    for (int i = start; i < end; i++) {
        uint2 a = __ldg(&g_adj[i]);                 // broadcast across 16 lanes
        float nv = __uint_as_float(a.y);
        uint2 u = __ldg(&hin[a.x * VEC + q]);
        float2 f0 = __half22float2(*reinterpret_cast<__half2*>(&u.x));
        float2 f1 = __half22float2(*reinterpret_cast<__half2*>(&u.y));
        acc.x += f0.x * nv; acc.y += f0.y * nv;
        acc.z += f1.x * nv; acc.w += f1.y * nv;
    }
    __half2 pa = __floats2half2_rn(acc.x, acc.y);
    __half2 pb = __floats2half2_rn(acc.z, acc.w);
    hout[t] = make_uint2(*reinterpret_cast<unsigned*>(&pa), *reinterpret_cast<unsigned*>(&pb));
}

// ---- ho = a0*h0 + a1*h1 + a2*h2 (all fp16 storage, fp32 math) ----
__global__ void k_combine(const float* __restrict__ alpha) {
    int t = blockIdx.x * blockDim.x + threadIdx.x;
    if (t >= N_NODES * VEC) return;
    float a0 = alpha[0], a1 = alpha[1], a2 = alpha[2];
    uint2 u0 = reinterpret_cast<uint2*>(g_h0)[t];
    uint2 u1 = reinterpret_cast<uint2*>(g_h1)[t];
    uint2 u2 = reinterpret_cast<uint2*>(g_h2)[t];
    float2 x0a = __half22float2(*reinterpret_cast<__half2*>(&u0.x));
    float2 x0b = __half22float2(*reinterpret_cast<__half2*>(&u0.y));
    float2 x1a = __half22float2(*reinterpret_cast<__half2*>(&u1.x));
    float2 x1b = __half22float2(*reinterpret_cast<__half2*>(&u1.y));
    float2 x2a = __half22float2(*reinterpret_cast<__half2*>(&u2.x));
    float2 x2b = __half22float2(*reinterpret_cast<__half2*>(&u2.y));
    __half2 pa = __floats2half2_rn(a0 * x0a.x + a1 * x1a.x + a2 * x2a.x,
                                   a0 * x0a.y + a1 * x1a.y + a2 * x2a.y);
    __half2 pb = __floats2half2_rn(a0 * x0b.x + a1 * x1b.x + a2 * x2b.x,
                                   a0 * x0b.y + a1 * x1b.y + a2 * x2b.y);
    reinterpret_cast<uint2*>(g_ho)[t] =
        make_uint2(*reinterpret_cast<unsigned*>(&pa), *reinterpret_cast<unsigned*>(&pb));
}

// ---- per-edge dot: 16 lanes/edge, shfl tree reduce ----
__global__ void k_dot(const int* __restrict__ row, const int* __restrict__ col,
                      float* __restrict__ out) {
    long long t = (long long)blockIdx.x * blockDim.x + threadIdx.x;
    if (t >= (long long)N_EDGES * VEC) return;
    int e = (int)(t >> 4), q = (int)(t & 15);
    const uint2* h = reinterpret_cast<const uint2*>(g_ho);
    uint2 ua = __ldg(&h[row[e] * VEC + q]);
    uint2 ub = __ldg(&h[col[e] * VEC + q]);
    float2 a0 = __half22float2(*reinterpret_cast<__half2*>(&ua.x));
    float2 a1 = __half22float2(*reinterpret_cast<__half2*>(&ua.y));
    float2 b0 = __half22float2(*reinterpret_cast<__half2*>(&ub.x));
    float2 b1 = __half22float2(*reinterpret_cast<__half2*>(&ub.y));
    float s = a0.x * b0.x + a0.y * b0.y + a1.x * b1.x + a1.y * b1.y;
    s += __shfl_xor_sync(0xffffffffu, s, 8);
    s += __shfl_xor_sync(0xffffffffu, s, 4);
    s += __shfl_xor_sync(0xffffffffu, s, 2);
    s += __shfl_xor_sync(0xffffffffu, s, 1);
    if (q == 0) out[e] = s;
}

// ---------------------------------------------------------------------------
extern "C" void kernel_launch(void* const* d_in, const int* in_sizes, int n_in,
                              void* d_out, int out_size) {
    const int*    edge_index = (const int*)d_in[0];       // [2, E]
    const int*    item_tag   = (const int*)d_in[1];
    const int*    item_testid= (const int*)d_in[2];
    const int*    item_bigcat= (const int*)d_in[3];
    const float4* user_emb   = (const float4*)d_in[4];
    const float4* item_emb   = (const float4*)d_in[5];
    const float4* tag_emb    = (const float4*)d_in[6];
    const float4* testid_emb = (const float4*)d_in[7];
    const float4* bigcat_emb = (const float4*)d_in[8];
    const float*  alpha      = (const float*)d_in[9];
    float* out = (float*)d_out;

    const int* row = edge_index;
    const int* col = edge_index + N_EDGES;

    const int B = 256;
    uint2* h0 = nullptr; uint2* h1 = nullptr; uint2* h2 = nullptr;
    cudaGetSymbolAddress((void**)&h0, g_h0);
    cudaGetSymbolAddress((void**)&h1, g_h1);
    cudaGetSymbolAddress((void**)&h2, g_h2);

    // degree, norm factors, CSR
    k_zero_counts<<<cdiv(N_NODES, B), B>>>();
    k_deg<<<cdiv(N_EDGES, B), B>>>(col);
    k_dis<<<cdiv(N_NODES, B), B>>>();
    k_scan_a<<<NB_SCAN, 256>>>();
    k_scan_b<<<1, 512>>>();
    k_scan_c<<<NB_SCAN, 256>>>();
    k_fill<<<cdiv(N_EDGES, B), B>>>(row, col);

    // features + 2 pull layers
    k_x0<<<cdiv(N_NODES * VEC, B), B>>>(user_emb, item_emb, item_tag, item_testid,
                                        item_bigcat, tag_emb, testid_emb, bigcat_emb);
    k_gather<<<cdiv(N_NODES * VEC, B), B>>>(h0, h1);
    k_gather<<<cdiv(N_NODES * VEC, B), B>>>(h1, h2);

    // combine + per-edge dots
    k_combine<<<cdiv(N_NODES * VEC, B), B>>>(alpha);
    k_dot<<<cdiv(N_EDGES * VEC, B), B>>>(row, col, out);
}

// round 4
// speedup vs baseline: 2.1429x; 1.3703x over previous
#include <cuda_runtime.h>
#include <cuda_fp16.h>

#define N_USER 100000
#define N_ITEM 20000
#define N_NODES 120000
#define N_EDGES 2000000
#define EMB 64
#define V4 8        // uint4 (8-half / 16B) chunks per 64-dim fp16 row
#define F4 16       // float4 chunks per 64-dim fp32 row
#define NB_SCAN 469 // cdiv(N_NODES, 256)

// ---- static scratch (no allocations allowed) ----
__device__ __half g_h0[N_NODES * EMB];   // fp16 feature buffers
__device__ __half g_h1[N_NODES * EMB];
__device__ __half g_ho[N_NODES * EMB];   // combined output embedding
__device__ int    g_deg[N_NODES];
__device__ int    g_cnt[N_NODES];
__device__ int    g_rowptr[N_NODES];
__device__ int    g_bsum[512];
__device__ float  g_dis[N_NODES];
__device__ uint2  g_adj[N_EDGES];        // {src, norm bits} grouped by dst

static inline int cdiv(int a, int b) { return (a + b - 1) / b; }

__device__ __forceinline__ float4 h8_mul_acc(float4 accA, uint4 u, float nv, float4* accB) {
    // interprets u as 8 halves; accumulates first 4 into accA, last 4 into *accB
    float2 f0 = __half22float2(*reinterpret_cast<__half2*>(&u.x));
    float2 f1 = __half22float2(*reinterpret_cast<__half2*>(&u.y));
    float2 f2 = __half22float2(*reinterpret_cast<__half2*>(&u.z));
    float2 f3 = __half22float2(*reinterpret_cast<__half2*>(&u.w));
    accA.x += f0.x * nv; accA.y += f0.y * nv;
    accA.z += f1.x * nv; accA.w += f1.y * nv;
    accB->x += f2.x * nv; accB->y += f2.y * nv;
    accB->z += f3.x * nv; accB->w += f3.y * nv;
    return accA;
}

__device__ __forceinline__ uint4 pack8(float4 a, float4 b) {
    __half2 p0 = __floats2half2_rn(a.x, a.y);
    __half2 p1 = __floats2half2_rn(a.z, a.w);
    __half2 p2 = __floats2half2_rn(b.x, b.y);
    __half2 p3 = __floats2half2_rn(b.z, b.w);
    return make_uint4(*reinterpret_cast<unsigned*>(&p0), *reinterpret_cast<unsigned*>(&p1),
                      *reinterpret_cast<unsigned*>(&p2), *reinterpret_cast<unsigned*>(&p3));
}

// ---------------------------------------------------------------------------
__global__ void k_zero_counts() {
    int n = blockIdx.x * blockDim.x + threadIdx.x;
    if (n < N_NODES) { g_deg[n] = 0; g_cnt[n] = 0; }
}

__global__ void k_deg(const int* __restrict__ col) {
    int e = blockIdx.x * blockDim.x + threadIdx.x;
    if (e < N_EDGES) atomicAdd(&g_deg[col[e]], 1);
}

__global__ void k_dis() {
    int n = blockIdx.x * blockDim.x + threadIdx.x;
    if (n < N_NODES) {
        int d = g_deg[n];
        g_dis[n] = (d > 0) ? rsqrtf((float)d) : 0.0f;
    }
}

// ---- 3-kernel exclusive scan of g_deg -> g_rowptr ----
__global__ void k_scan_a() {
    __shared__ int sh[256];
    int i = blockIdx.x * 256 + threadIdx.x;
    sh[threadIdx.x] = (i < N_NODES) ? g_deg[i] : 0;
    __syncthreads();
    for (int s = 128; s > 0; s >>= 1) {
        if (threadIdx.x < s) sh[threadIdx.x] += sh[threadIdx.x + s];
        __syncthreads();
    }
    if (threadIdx.x == 0) g_bsum[blockIdx.x] = sh[0];
}

__global__ void k_scan_b() {
    __shared__ int sh[512];
    int t = threadIdx.x;
    int v = (t < NB_SCAN) ? g_bsum[t] : 0;
    sh[t] = v;
    __syncthreads();
    for (int off = 1; off < 512; off <<= 1) {
        int x = (t >= off) ? sh[t - off] : 0;
        __syncthreads();
        sh[t] += x;
        __syncthreads();
    }
    if (t < NB_SCAN) g_bsum[t] = sh[t] - v;   // exclusive prefix of block sums
}

__global__ void k_scan_c() {
    __shared__ int sh[256];
    int i = blockIdx.x * 256 + threadIdx.x;
    int v = (i < N_NODES) ? g_deg[i] : 0;
    sh[threadIdx.x] = v;
    __syncthreads();
    for (int off = 1; off < 256; off <<= 1) {
        int x = (threadIdx.x >= off) ? sh[threadIdx.x - off] : 0;
        __syncthreads();
        sh[threadIdx.x] += x;
        __syncthreads();
    }
    if (i < N_NODES) g_rowptr[i] = g_bsum[blockIdx.x] + sh[threadIdx.x] - v;
}

// ---- CSR fill: slot per edge under its destination ----
__global__ void k_fill(const int* __restrict__ row, const int* __restrict__ col) {
    int e = blockIdx.x * blockDim.x + threadIdx.x;
    if (e >= N_EDGES) return;
    int r = row[e], c = col[e];
    float nv = g_dis[r] * g_dis[c];
    int pos = g_rowptr[c] + atomicAdd(&g_cnt[c], 1);
    g_adj[pos] = make_uint2((unsigned)r, __float_as_uint(nv));
}

// ---- x0: users copied, items = mean of 4 embeddings; fp16 out (8 lanes/row) --
__global__ void k_x0(const float4* __restrict__ user_emb,
                     const float4* __restrict__ item_emb,
                     const int*    __restrict__ tag,
                     const int*    __restrict__ testid,
                     const int*    __restrict__ bigcat,
                     const float4* __restrict__ tag_emb,
                     const float4* __restrict__ testid_emb,
                     const float4* __restrict__ bigcat_emb) {
    int t = blockIdx.x * blockDim.x + threadIdx.x;   // one thread = 8 floats = 2 float4
    if (t >= N_NODES * V4) return;
    int n = t >> 3, q = t & 7;                        // q: which 16B chunk
    float4 va, vb;
    if (n < N_USER) {
        va = user_emb[n * F4 + 2 * q];
        vb = user_emb[n * F4 + 2 * q + 1];
    } else {
        int i = n - N_USER;
        int tg = tag[i] * F4, ts = testid[i] * F4, bc = bigcat[i] * F4;
        float4 a0 = item_emb[i * F4 + 2 * q],     a1 = item_emb[i * F4 + 2 * q + 1];
        float4 b0 = tag_emb[tg + 2 * q],          b1 = tag_emb[tg + 2 * q + 1];
        float4 c0 = testid_emb[ts + 2 * q],       c1 = testid_emb[ts + 2 * q + 1];
        float4 d0 = bigcat_emb[bc + 2 * q],       d1 = bigcat_emb[bc + 2 * q + 1];
        va = make_float4((a0.x + b0.x + c0.x + d0.x) * 0.25f,
                         (a0.y + b0.y + c0.y + d0.y) * 0.25f,
                         (a0.z + b0.z + c0.z + d0.z) * 0.25f,
                         (a0.w + b0.w + c0.w + d0.w) * 0.25f);
        vb = make_float4((a1.x + b1.x + c1.x + d1.x) * 0.25f,
                         (a1.y + b1.y + c1.y + d1.y) * 0.25f,
                         (a1.z + b1.z + c1.z + d1.z) * 0.25f,
                         (a1.w + b1.w + c1.w + d1.w) * 0.25f);
    }
    reinterpret_cast<uint4*>(g_h0)[t] = pack8(va, vb);
}

// ---- pull layer 1: 8 lanes per dst node, uint4 row loads ----
__global__ void k_gather(const uint4* __restrict__ hin, uint4* __restrict__ hout) {
    int t = blockIdx.x * blockDim.x + threadIdx.x;
    if (t >= N_NODES * V4) return;
    int n = t >> 3, q = t & 7;
    int start = g_rowptr[n];
    int end = start + g_deg[n];
    float4 accA = make_float4(0.f, 0.f, 0.f, 0.f);
    float4 accB = make_float4(0.f, 0.f, 0.f, 0.f);
    #pragma unroll 4
    for (int i = start; i < end; i++) {
        uint2 a = __ldg(&g_adj[i]);
        float nv = __uint_as_float(a.y);
        uint4 u = __ldg(&hin[a.x * V4 + q]);
        accA = h8_mul_acc(accA, u, nv, &accB);
    }
    hout[t] = pack8(accA, accB);
}

// ---- pull layer 2 fused with combine: ho = a0*h0 + a1*h1 + a2*(A h1) ----
__global__ void k_gather_combine(const uint4* __restrict__ h0,
                                 const uint4* __restrict__ h1,
                                 uint4* __restrict__ ho,
                                 const float* __restrict__ alpha) {
    int t = blockIdx.x * blockDim.x + threadIdx.x;
    if (t >= N_NODES * V4) return;
    int n = t >> 3, q = t & 7;
    int start = g_rowptr[n];
    int end = start + g_deg[n];
    float4 accA = make_float4(0.f, 0.f, 0.f, 0.f);
    float4 accB = make_float4(0.f, 0.f, 0.f, 0.f);
    #pragma unroll 4
    for (int i = start; i < end; i++) {
        uint2 a = __ldg(&g_adj[i]);
        float nv = __uint_as_float(a.y);
        uint4 u = __ldg(&h1[a.x * V4 + q]);
        accA = h8_mul_acc(accA, u, nv, &accB);
    }
    float a0 = alpha[0], a1 = alpha[1], a2 = alpha[2];
    // scale layer-2 term by a2, add a0*h0 + a1*h1 (coalesced reads at t)
    accA.x *= a2; accA.y *= a2; accA.z *= a2; accA.w *= a2;
    accB.x *= a2; accB.y *= a2; accB.z *= a2; accB.w *= a2;
    uint4 u0 = h0[t];
    accA = h8_mul_acc(accA, u0, a0, &accB);
    uint4 u1 = h1[t];
    accA = h8_mul_acc(accA, u1, a1, &accB);
    ho[t] = pack8(accA, accB);
}

// ---- per-edge dot: 8 lanes/edge, uint4 loads, shfl tree reduce ----
__global__ void k_dot(const int* __restrict__ row, const int* __restrict__ col,
                      float* __restrict__ out) {
    int t = blockIdx.x * blockDim.x + threadIdx.x;
    if (t >= N_EDGES * V4) return;
    int e = t >> 3, q = t & 7;
    const uint4* h = reinterpret_cast<const uint4*>(g_ho);
    uint4 ua = __ldg(&h[row[e] * V4 + q]);
    uint4 ub = __ldg(&h[col[e] * V4 + q]);
    float2 a0 = __half22float2(*reinterpret_cast<__half2*>(&ua.x));
    float2 a1 = __half22float2(*reinterpret_cast<__half2*>(&ua.y));
    float2 a2 = __half22float2(*reinterpret_cast<__half2*>(&ua.z));
    float2 a3 = __half22float2(*reinterpret_cast<__half2*>(&ua.w));
    float2 b0 = __half22float2(*reinterpret_cast<__half2*>(&ub.x));
    float2 b1 = __half22float2(*reinterpret_cast<__half2*>(&ub.y));
    float2 b2 = __half22float2(*reinterpret_cast<__half2*>(&ub.z));
    float2 b3 = __half22float2(*reinterpret_cast<__half2*>(&ub.w));
    float s = a0.x * b0.x + a0.y * b0.y + a1.x * b1.x + a1.y * b1.y
            + a2.x * b2.x + a2.y * b2.y + a3.x * b3.x + a3.y * b3.y;
    s += __shfl_xor_sync(0xffffffffu, s, 4);
    s += __shfl_xor_sync(0xffffffffu, s, 2);
    s += __shfl_xor_sync(0xffffffffu, s, 1);
    if (q == 0) out[e] = s;
}

// ---------------------------------------------------------------------------
extern "C" void kernel_launch(void* const* d_in, const int* in_sizes, int n_in,
                              void* d_out, int out_size) {
    const int*    edge_index = (const int*)d_in[0];       // [2, E]
    const int*    item_tag   = (const int*)d_in[1];
    const int*    item_testid= (const int*)d_in[2];
    const int*    item_bigcat= (const int*)d_in[3];
    const float4* user_emb   = (const float4*)d_in[4];
    const float4* item_emb   = (const float4*)d_in[5];
    const float4* tag_emb    = (const float4*)d_in[6];
    const float4* testid_emb = (const float4*)d_in[7];
    const float4* bigcat_emb = (const float4*)d_in[8];
    const float*  alpha      = (const float*)d_in[9];
    float* out = (float*)d_out;

    const int* row = edge_index;
    const int* col = edge_index + N_EDGES;

    const int B = 256;
    uint4* h0 = nullptr; uint4* h1 = nullptr; uint4* ho = nullptr;
    cudaGetSymbolAddress((void**)&h0, g_h0);
    cudaGetSymbolAddress((void**)&h1, g_h1);
    cudaGetSymbolAddress((void**)&ho, g_ho);

    // degree, norm factors, CSR
    k_zero_counts<<<cdiv(N_NODES, B), B>>>();
    k_deg<<<cdiv(N_EDGES, B), B>>>(col);
    k_dis<<<cdiv(N_NODES, B), B>>>();
    k_scan_a<<<NB_SCAN, 256>>>();
    k_scan_b<<<1, 512>>>();
    k_scan_c<<<NB_SCAN, 256>>>();
    k_fill<<<cdiv(N_EDGES, B), B>>>(row, col);

    // features + 2 pull layers (second fused with combine)
    k_x0<<<cdiv(N_NODES * V4, B), B>>>(user_emb, item_emb, item_tag, item_testid,
                                       item_bigcat, tag_emb, testid_emb, bigcat_emb);
    k_gather<<<cdiv(N_NODES * V4, B), B>>>(h0, h1);
    k_gather_combine<<<cdiv(N_NODES * V4, B), B>>>(h0, h1, ho, alpha);

    // per-edge dots
    k_dot<<<cdiv(N_EDGES * V4, B), B>>>(row, col, out);
}

// round 5
// speedup vs baseline: 2.3115x; 1.0787x over previous
#include <cuda_runtime.h>
#include <cuda_fp16.h>

#define N_USER 100000
#define N_ITEM 20000
#define N_NODES 120000
#define N_EDGES 2000000
#define EMB 64
#define V4 8        // uint4 (8-half / 16B) chunks per 64-dim fp16 row
#define F4 16       // float4 chunks per 64-dim fp32 row
#define NB_SCAN 469 // cdiv(N_NODES, 256)

// ---- static scratch (no allocations allowed) ----
__device__ __half g_h0[N_NODES * EMB];   // fp16 feature buffers
__device__ __half g_h1[N_NODES * EMB];
__device__ __half g_ho[N_NODES * EMB];   // combined output embedding
__device__ int    g_deg[N_NODES];
__device__ int    g_cnt[N_NODES];
__device__ int    g_rowptr[N_NODES];
__device__ int    g_bsum[512];
__device__ float  g_dis[N_NODES];
__device__ uint2  g_adj[N_EDGES];        // {src, norm bits} grouped by dst
__device__ int    g_eid[N_EDGES];        // original edge index per CSR slot

static inline int cdiv(int a, int b) { return (a + b - 1) / b; }

__device__ __forceinline__ float4 h8_mul_acc(float4 accA, uint4 u, float nv, float4* accB) {
    float2 f0 = __half22float2(*reinterpret_cast<__half2*>(&u.x));
    float2 f1 = __half22float2(*reinterpret_cast<__half2*>(&u.y));
    float2 f2 = __half22float2(*reinterpret_cast<__half2*>(&u.z));
    float2 f3 = __half22float2(*reinterpret_cast<__half2*>(&u.w));
    accA.x += f0.x * nv; accA.y += f0.y * nv;
    accA.z += f1.x * nv; accA.w += f1.y * nv;
    accB->x += f2.x * nv; accB->y += f2.y * nv;
    accB->z += f3.x * nv; accB->w += f3.y * nv;
    return accA;
}

__device__ __forceinline__ uint4 pack8(float4 a, float4 b) {
    __half2 p0 = __floats2half2_rn(a.x, a.y);
    __half2 p1 = __floats2half2_rn(a.z, a.w);
    __half2 p2 = __floats2half2_rn(b.x, b.y);
    __half2 p3 = __floats2half2_rn(b.z, b.w);
    return make_uint4(*reinterpret_cast<unsigned*>(&p0), *reinterpret_cast<unsigned*>(&p1),
                      *reinterpret_cast<unsigned*>(&p2), *reinterpret_cast<unsigned*>(&p3));
}

// ---------------------------------------------------------------------------
__global__ void k_zero_counts() {
    int n = blockIdx.x * blockDim.x + threadIdx.x;
    if (n < N_NODES) { g_deg[n] = 0; g_cnt[n] = 0; }
}

__global__ void k_deg(const int* __restrict__ col) {
    int e = blockIdx.x * blockDim.x + threadIdx.x;
    if (e < N_EDGES) atomicAdd(&g_deg[col[e]], 1);
}

// ---- scan_a fused with dis: block sums of deg + per-node rsqrt ----
__global__ void k_scan_a_dis() {
    __shared__ int sh[256];
    int i = blockIdx.x * 256 + threadIdx.x;
    int d = (i < N_NODES) ? g_deg[i] : 0;
    if (i < N_NODES) g_dis[i] = (d > 0) ? rsqrtf((float)d) : 0.0f;
    sh[threadIdx.x] = d;
    __syncthreads();
    for (int s = 128; s > 0; s >>= 1) {
        if (threadIdx.x < s) sh[threadIdx.x] += sh[threadIdx.x + s];
        __syncthreads();
    }
    if (threadIdx.x == 0) g_bsum[blockIdx.x] = sh[0];
}

__global__ void k_scan_b() {
    __shared__ int sh[512];
    int t = threadIdx.x;
    int v = (t < NB_SCAN) ? g_bsum[t] : 0;
    sh[t] = v;
    __syncthreads();
    for (int off = 1; off < 512; off <<= 1) {
        int x = (t >= off) ? sh[t - off] : 0;
        __syncthreads();
        sh[t] += x;
        __syncthreads();
    }
    if (t < NB_SCAN) g_bsum[t] = sh[t] - v;   // exclusive prefix of block sums
}

__global__ void k_scan_c() {
    __shared__ int sh[256];
    int i = blockIdx.x * 256 + threadIdx.x;
    int v = (i < N_NODES) ? g_deg[i] : 0;
    sh[threadIdx.x] = v;
    __syncthreads();
    for (int off = 1; off < 256; off <<= 1) {
        int x = (threadIdx.x >= off) ? sh[threadIdx.x - off] : 0;
        __syncthreads();
        sh[threadIdx.x] += x;
        __syncthreads();
    }
    if (i < N_NODES) g_rowptr[i] = g_bsum[blockIdx.x] + sh[threadIdx.x] - v;
}

// ---- CSR fill: slot per edge under its destination; also record edge id ----
__global__ void k_fill(const int* __restrict__ row, const int* __restrict__ col) {
    int e = blockIdx.x * blockDim.x + threadIdx.x;
    if (e >= N_EDGES) return;
    int r = row[e], c = col[e];
    float nv = g_dis[r] * g_dis[c];
    int pos = g_rowptr[c] + atomicAdd(&g_cnt[c], 1);
    g_adj[pos] = make_uint2((unsigned)r, __float_as_uint(nv));
    g_eid[pos] = e;
}

// ---- x0: users copied, items = mean of 4 embeddings; fp16 out (8 lanes/row) --
__global__ void k_x0(const float4* __restrict__ user_emb,
                     const float4* __restrict__ item_emb,
                     const int*    __restrict__ tag,
                     const int*    __restrict__ testid,
                     const int*    __restrict__ bigcat,
                     const float4* __restrict__ tag_emb,
                     const float4* __restrict__ testid_emb,
                     const float4* __restrict__ bigcat_emb) {
    int t = blockIdx.x * blockDim.x + threadIdx.x;
    if (t >= N_NODES * V4) return;
    int n = t >> 3, q = t & 7;
    float4 va, vb;
    if (n < N_USER) {
        va = user_emb[n * F4 + 2 * q];
        vb = user_emb[n * F4 + 2 * q + 1];
    } else {
        int i = n - N_USER;
        int tg = tag[i] * F4, ts = testid[i] * F4, bc = bigcat[i] * F4;
        float4 a0 = item_emb[i * F4 + 2 * q],     a1 = item_emb[i * F4 + 2 * q + 1];
        float4 b0 = tag_emb[tg + 2 * q],          b1 = tag_emb[tg + 2 * q + 1];
        float4 c0 = testid_emb[ts + 2 * q],       c1 = testid_emb[ts + 2 * q + 1];
        float4 d0 = bigcat_emb[bc + 2 * q],       d1 = bigcat_emb[bc + 2 * q + 1];
        va = make_float4((a0.x + b0.x + c0.x + d0.x) * 0.25f,
                         (a0.y + b0.y + c0.y + d0.y) * 0.25f,
                         (a0.z + b0.z + c0.z + d0.z) * 0.25f,
                         (a0.w + b0.w + c0.w + d0.w) * 0.25f);
        vb = make_float4((a1.x + b1.x + c1.x + d1.x) * 0.25f,
                         (a1.y + b1.y + c1.y + d1.y) * 0.25f,
                         (a1.z + b1.z + c1.z + d1.z) * 0.25f,
                         (a1.w + b1.w + c1.w + d1.w) * 0.25f);
    }
    reinterpret_cast<uint4*>(g_h0)[t] = pack8(va, vb);
}

// ---- pull layer 1: 8 lanes per dst node, uint4 row loads ----
__global__ void k_gather(const uint4* __restrict__ hin, uint4* __restrict__ hout) {
    int t = blockIdx.x * blockDim.x + threadIdx.x;
    if (t >= N_NODES * V4) return;
    int n = t >> 3, q = t & 7;
    int start = g_rowptr[n];
    int end = start + g_deg[n];
    float4 accA = make_float4(0.f, 0.f, 0.f, 0.f);
    float4 accB = make_float4(0.f, 0.f, 0.f, 0.f);
    #pragma unroll 4
    for (int i = start; i < end; i++) {
        uint2 a = __ldg(&g_adj[i]);
        float nv = __uint_as_float(a.y);
        uint4 u = __ldg(&hin[a.x * V4 + q]);
        accA = h8_mul_acc(accA, u, nv, &accB);
    }
    hout[t] = pack8(accA, accB);
}

// ---- pull layer 2 fused with combine: ho = a0*h0 + a1*h1 + a2*(A h1) ----
__global__ void k_gather_combine(const uint4* __restrict__ h0,
                                 const uint4* __restrict__ h1,
                                 uint4* __restrict__ ho,
                                 const float* __restrict__ alpha) {
    int t = blockIdx.x * blockDim.x + threadIdx.x;
    if (t >= N_NODES * V4) return;
    int n = t >> 3, q = t & 7;
    int start = g_rowptr[n];
    int end = start + g_deg[n];
    float4 accA = make_float4(0.f, 0.f, 0.f, 0.f);
    float4 accB = make_float4(0.f, 0.f, 0.f, 0.f);
    #pragma unroll 4
    for (int i = start; i < end; i++) {
        uint2 a = __ldg(&g_adj[i]);
        float nv = __uint_as_float(a.y);
        uint4 u = __ldg(&h1[a.x * V4 + q]);
        accA = h8_mul_acc(accA, u, nv, &accB);
    }
    float a0 = alpha[0], a1 = alpha[1], a2 = alpha[2];
    accA.x *= a2; accA.y *= a2; accA.z *= a2; accA.w *= a2;
    accB.x *= a2; accB.y *= a2; accB.z *= a2; accB.w *= a2;
    uint4 u0 = h0[t];
    accA = h8_mul_acc(accA, u0, a0, &accB);
    uint4 u1 = h1[t];
    accA = h8_mul_acc(accA, u1, a1, &accB);
    ho[t] = pack8(accA, accB);
}

// ---- per-edge dots in CSR order: dst row register-resident, src row random --
__global__ void k_dot_csr(float* __restrict__ out) {
    int t = blockIdx.x * blockDim.x + threadIdx.x;
    if (t >= N_NODES * V4) return;
    int n = t >> 3, q = t & 7;
    int start = g_rowptr[n];
    int end = start + g_deg[n];
    if (start == end) return;
    unsigned gmask = 0xFFu << (threadIdx.x & 24);   // this thread's 8-lane group
    const uint4* h = reinterpret_cast<const uint4*>(g_ho);
    uint4 uc = h[n * V4 + q];                        // dst row chunk, loop-invariant
    float2 c0 = __half22float2(*reinterpret_cast<__half2*>(&uc.x));
    float2 c1 = __half22float2(*reinterpret_cast<__half2*>(&uc.y));
    float2 c2 = __half22float2(*reinterpret_cast<__half2*>(&uc.z));
    float2 c3 = __half22float2(*reinterpret_cast<__half2*>(&uc.w));
    for (int i = start; i < end; i++) {
        uint2 a = __ldg(&g_adj[i]);
        int eid = __ldg(&g_eid[i]);
        uint4 ua = __ldg(&h[a.x * V4 + q]);
        float2 s0 = __half22float2(*reinterpret_cast<__half2*>(&ua.x));
        float2 s1 = __half22float2(*reinterpret_cast<__half2*>(&ua.y));
        float2 s2 = __half22float2(*reinterpret_cast<__half2*>(&ua.z));
        float2 s3 = __half22float2(*reinterpret_cast<__half2*>(&ua.w));
        float s = s0.x * c0.x + s0.y * c0.y + s1.x * c1.x + s1.y * c1.y
                + s2.x * c2.x + s2.y * c2.y + s3.x * c3.x + s3.y * c3.y;
        s += __shfl_xor_sync(gmask, s, 4);
        s += __shfl_xor_sync(gmask, s, 2);
        s += __shfl_xor_sync(gmask, s, 1);
        if (q == 0) out[eid] = s;
    }
}

// ---------------------------------------------------------------------------
extern "C" void kernel_launch(void* const* d_in, const int* in_sizes, int n_in,
                              void* d_out, int out_size) {
    const int*    edge_index = (const int*)d_in[0];       // [2, E]
    const int*    item_tag   = (const int*)d_in[1];
    const int*    item_testid= (const int*)d_in[2];
    const int*    item_bigcat= (const int*)d_in[3];
    const float4* user_emb   = (const float4*)d_in[4];
    const float4* item_emb   = (const float4*)d_in[5];
    const float4* tag_emb    = (const float4*)d_in[6];
    const float4* testid_emb = (const float4*)d_in[7];
    const float4* bigcat_emb = (const float4*)d_in[8];
    const float*  alpha      = (const float*)d_in[9];
    float* out = (float*)d_out;

    const int* row = edge_index;
    const int* col = edge_index + N_EDGES;

    const int B = 256;
    uint4* h0 = nullptr; uint4* h1 = nullptr; uint4* ho = nullptr;
    cudaGetSymbolAddress((void**)&h0, g_h0);
    cudaGetSymbolAddress((void**)&h1, g_h1);
    cudaGetSymbolAddress((void**)&ho, g_ho);

    // degree, norm factors, CSR (with edge ids)
    k_zero_counts<<<cdiv(N_NODES, B), B>>>();
    k_deg<<<cdiv(N_EDGES, B), B>>>(col);
    k_scan_a_dis<<<NB_SCAN, 256>>>();
    k_scan_b<<<1, 512>>>();
    k_scan_c<<<NB_SCAN, 256>>>();
    k_fill<<<cdiv(N_EDGES, B), B>>>(row, col);

    // features + 2 pull layers (second fused with combine)
    k_x0<<<cdiv(N_NODES * V4, B), B>>>(user_emb, item_emb, item_tag, item_testid,
                                       item_bigcat, tag_emb, testid_emb, bigcat_emb);
    k_gather<<<cdiv(N_NODES * V4, B), B>>>(h0, h1);
    k_gather_combine<<<cdiv(N_NODES * V4, B), B>>>(h0, h1, ho, alpha);

    // per-edge dots via CSR traversal
    k_dot_csr<<<cdiv(N_NODES * V4, B), B>>>(out);
}